// round 13
// baseline (speedup 1.0000x reference)
#include <cuda_runtime.h>
#include <cstddef>

#define N_NODES   60000
#define N_EDGES   240000
#define WIDTH     256
#define DIM_HEAD  32
#define NUM_HEAD  8
#define MTILE     32

// ---------------------------------------------------------------------------
// Device scratch
// ---------------------------------------------------------------------------
__device__ float g_aggx[(size_t)N_NODES * WIDTH];     // segment_sum(x[i0])
__device__ float g_t2  [(size_t)N_NODES * DIM_HEAD];  // segment_sum(t2)
__device__ int   g_indeg[N_NODES];
__device__ float g_xld [(size_t)N_NODES * DIM_HEAD];  // x @ lora_down

// mma-B-fragment swizzled weights (tf32-rounded fp32 bit patterns)
__device__ float g_W2f[36 * 64 * 32 * 2];          // W2 288x512: [ks][col8][lane][2]
__device__ float g_GVf[2 * 8 * 4 * 16 * 32 * 2];   // gate/value kernels
__device__ float g_Pf [8 * 16 * 4 * 32 * 2];       // post kernel

__device__ __forceinline__ float sp(float x) {
    return fmaxf(x, 0.f) + log1pf(expf(-fabsf(x)));
}
__device__ __forceinline__ float wsum(float v) {
#pragma unroll
    for (int o = 16; o; o >>= 1) v += __shfl_xor_sync(0xffffffffu, v, o);
    return v;
}
__device__ __forceinline__ void red_add_v4(float* p, float4 v) {
    asm volatile("red.global.add.v4.f32 [%0], {%1, %2, %3, %4};"
                 :: "l"(p), "f"(v.x), "f"(v.y), "f"(v.z), "f"(v.w)
                 : "memory");
}
__device__ __forceinline__ float tf32r(float f) {
    unsigned r;
    asm("cvt.rna.tf32.f32 %0, %1;" : "=r"(r) : "f"(f));
    return __uint_as_float(r);
}
__device__ __forceinline__ void mma_tf32(float4& c,
    unsigned a0, unsigned a1, unsigned a2, unsigned a3,
    unsigned b0, unsigned b1)
{
    asm volatile(
        "mma.sync.aligned.m16n8k8.row.col.f32.tf32.tf32.f32 "
        "{%0,%1,%2,%3},{%4,%5,%6,%7},{%8,%9},{%0,%1,%2,%3};"
        : "+f"(c.x), "+f"(c.y), "+f"(c.z), "+f"(c.w)
        : "r"(a0), "r"(a1), "r"(a2), "r"(a3), "r"(b0), "r"(b1));
}

// ---------------------------------------------------------------------------
// init_kernel: blocks [0,1875) xld via mma (4 rotating accumulators);
//              blocks [1875,2899) zero g_aggx/g_t2/g_indeg.
// ---------------------------------------------------------------------------
__global__ __launch_bounds__(256) void init_kernel(
    const float* __restrict__ x,
    const float* __restrict__ lora_down)
{
    const int b = blockIdx.x, tid = threadIdx.x;
    if (b < 1875) {
        extern __shared__ float xs[];      // [32][260]
        const int nb = b * 32;
        const int lane = tid & 31, wid = tid >> 5;
        const int g = lane >> 2, t = lane & 3;
        {
            const int n  = tid >> 3;
            const int c0 = (tid & 7) * 4;
            const int gcl = min(nb + n, N_NODES - 1);
            const float* xr = x + (size_t)gcl * WIDTH;
#pragma unroll
            for (int it = 0; it < 8; it++) {
                int c = c0 + it * 32;
                float4 v = __ldg((const float4*)(xr + c));
                xs[n * 260 + c + 0] = tf32r(v.x);
                xs[n * 260 + c + 1] = tf32r(v.y);
                xs[n * 260 + c + 2] = tf32r(v.z);
                xs[n * 260 + c + 3] = tf32r(v.w);
            }
        }
        __syncthreads();
        const int wm = wid >> 2, wn = wid & 3;   // 2 M x 4 N
        const unsigned* Xu = (const unsigned*)xs;
        const int r = (wm * 16 + g) * 260;
        float4 acc[4];
#pragma unroll
        for (int q = 0; q < 4; q++) acc[q] = make_float4(0.f, 0.f, 0.f, 0.f);
#pragma unroll 4
        for (int ks = 0; ks < 32; ks++) {
            int kc = ks * 8 + t;
            unsigned a0 = Xu[r + kc];
            unsigned a1 = Xu[r + 2080 + kc];
            unsigned a2 = Xu[r + kc + 4];
            unsigned a3 = Xu[r + 2080 + kc + 4];
            unsigned b0 = __float_as_uint(
                tf32r(__ldg(&lora_down[(ks * 8 + t) * 32 + wn * 8 + g])));
            unsigned b1 = __float_as_uint(
                tf32r(__ldg(&lora_down[(ks * 8 + 4 + t) * 32 + wn * 8 + g])));
            mma_tf32(acc[ks & 3], a0, a1, a2, a3, b0, b1);
        }
        float4 s;
        s.x = (acc[0].x + acc[1].x) + (acc[2].x + acc[3].x);
        s.y = (acc[0].y + acc[1].y) + (acc[2].y + acc[3].y);
        s.z = (acc[0].z + acc[1].z) + (acc[2].z + acc[3].z);
        s.w = (acc[0].w + acc[1].w) + (acc[2].w + acc[3].w);
        int col = wn * 8 + 2 * t;
        int row0 = nb + wm * 16 + g;
        if (row0 < N_NODES)
            *(float2*)&g_xld[(size_t)row0 * 32 + col] = make_float2(s.x, s.y);
        if (row0 + 8 < N_NODES)
            *(float2*)&g_xld[(size_t)(row0 + 8) * 32 + col] = make_float2(s.z, s.w);
    } else {
        size_t i0 = (size_t)(b - 1875) * 256 + tid;
        size_t step = (size_t)1024 * 256;
        size_t n4 = (size_t)N_NODES * WIDTH / 4;
        float4* p = (float4*)g_aggx;
        for (size_t i = i0; i < n4; i += step)
            p[i] = make_float4(0.f, 0.f, 0.f, 0.f);
        size_t m4 = (size_t)N_NODES * DIM_HEAD / 4;
        float4* q4 = (float4*)g_t2;
        for (size_t i = i0; i < m4; i += step)
            q4[i] = make_float4(0.f, 0.f, 0.f, 0.f);
        for (size_t i = i0; i < N_NODES; i += step)
            g_indeg[i] = 0;
    }
}

// ---------------------------------------------------------------------------
// work_kernel: blocks [0,7500) edge ; [7500,7644) W2 gemm+swizzle ;
// [7644,7900) gate/value swizzle ; [7900,8028) post swizzle.
// ---------------------------------------------------------------------------
__global__ __launch_bounds__(256) void work_kernel(
    const float* __restrict__ x,
    const int*   __restrict__ edge_idx,
    const int*   __restrict__ edge_attr,
    const float* __restrict__ node_elec,
    const float* __restrict__ emb_edge,
    const float* __restrict__ moa_w,
    const float* __restrict__ moa_s,
    const float* __restrict__ elec_lin,
    const float* __restrict__ lin_pre,
    const float* __restrict__ lora_up,
    const float* __restrict__ gate_lin,
    const float* __restrict__ value_lin,
    const float* __restrict__ gate_kernel,
    const float* __restrict__ value_kernel,
    const float* __restrict__ post_kernel)
{
    __shared__ int   s_i0[32], s_i1[32];
    __shared__ float emb_s[32][33];

    const int b = blockIdx.x, tid = threadIdx.x;

    if (b < 7500) {
        const int eb = b * 32;
        if (tid < 32) {
            int i0 = edge_idx[eb + tid];
            int i1 = edge_idx[N_EDGES + eb + tid];
            s_i0[tid] = i0;
            s_i1[tid] = i1;
            atomicAdd(&g_indeg[i1], 1);
        }
        __syncthreads();
        {
            const int wid = tid >> 5, lane = tid & 31;
            float w0 = sp(moa_w[lane]);
            float w1 = sp(moa_w[32 + lane]);
            w0 /= wsum(w0);
            w1 /= wsum(w1);
            const float s0  = sp(moa_s[lane]);
            const float s1  = sp(moa_s[32 + lane]);
            const float el0 = elec_lin[lane];
            const float el1 = elec_lin[32 + lane];
#pragma unroll
            for (int i = 0; i < 4; i++) {
                int e  = wid * 4 + i;
                int i0 = s_i0[e], i1 = s_i1[e];
                float d0 = node_elec[2 * i0]     - node_elec[2 * i1];
                float d1 = node_elec[2 * i0 + 1] - node_elec[2 * i1 + 1];
                float m0 = wsum(tanhf(d0 * s0) * w0);
                float m1 = wsum(tanhf(d1 * s1) * w1);
                int ge = eb + e;
                int a0 = edge_attr[3 * ge], a1 = edge_attr[3 * ge + 1],
                    a2 = edge_attr[3 * ge + 2];
                emb_s[e][lane] = emb_edge[a0 * 32 + lane] + emb_edge[a1 * 32 + lane] +
                                 emb_edge[a2 * 32 + lane] + m0 * el0 + m1 * el1;
            }
        }
        __syncthreads();

        const int e  = tid >> 3;
        const int i0 = s_i0[e], i1 = s_i1[e];
        {
            const int d = (tid & 7) * 4;
            float4 a = __ldg((const float4*)(g_xld + (size_t)i0 * 32 + d));
            float4 bb = __ldg((const float4*)(g_xld + (size_t)i1 * 32 + d));
            float4 t;
            t.x = (a.x + bb.x) * emb_s[e][d + 0];
            t.y = (a.y + bb.y) * emb_s[e][d + 1];
            t.z = (a.z + bb.z) * emb_s[e][d + 2];
            t.w = (a.w + bb.w) * emb_s[e][d + 3];
            red_add_v4(g_t2 + (size_t)i1 * 32 + d, t);
        }
        {
            const int c0 = (tid & 7) * 4;
            const float4* xr = (const float4*)(x + (size_t)i0 * WIDTH);
            float* dst = g_aggx + (size_t)i1 * WIDTH;
#pragma unroll
            for (int it = 0; it < 8; it++) {
                int c = c0 + it * 32;
                float4 v = __ldg(&xr[c >> 2]);
                red_add_v4(dst + c, v);
            }
        }
    } else if (b < 7644) {
        int id = (b - 7500) * 256 + tid;   // 36864
        int k  = id >> 7;                  // 0..287
        int n  = (id & 127) * 4;           // 0..508
        const float* srow = (k < 256) ? (lin_pre + k * 256)
                                      : (lora_up + (k - 256) * 256);
        const float* M = (n < 256) ? gate_lin : value_lin;
        int nn = n & 255;
        float4 acc = make_float4(0.f, 0.f, 0.f, 0.f);
#pragma unroll 4
        for (int j = 0; j < 256; j++) {
            float  s = __ldg(&srow[j]);
            float4 m = __ldg((const float4*)(M + j * 256 + nn));
            acc.x += s * m.x; acc.y += s * m.y;
            acc.z += s * m.z; acc.w += s * m.w;
        }
        int ks = k >> 3, kin = k & 7, tig = kin & 3, jj = kin >> 2;
        float v[4] = {acc.x, acc.y, acc.z, acc.w};
#pragma unroll
        for (int q = 0; q < 4; q++) {
            int nq = n + q;
            int idx = ((ks * 64 + (nq >> 3)) * 32 + ((nq & 7) * 4 + tig)) * 2 + jj;
            g_W2f[idx] = tf32r(v[q]);
        }
    } else if (b < 7900) {
        int id = (b - 7644) * 256 + tid;   // 65536
        int path = id >> 15;
        int h    = (id >> 12) & 7;
        int d    = (id >> 7) & 31;
        int f    = id & 127;
        float val = path ? __ldg(&value_kernel[h * 4096 + d * 128 + f])
                         : __ldg(&gate_kernel [h * 4096 + d * 128 + f]);
        int ks = d >> 3, kin = d & 7, tig = kin & 3, jj = kin >> 2;
        int nt = f >> 3, g = f & 7;
        int idx = (((((path * 8 + h) * 4 + ks) * 16 + nt) * 32) + (g * 4 + tig)) * 2 + jj;
        g_GVf[idx] = tf32r(val);
    } else {
        int p = (b - 7900) * 256 + tid;    // 32768
        int h = p >> 12;
        int f = (p >> 5) & 127;
        int d2 = p & 31;
        float val = __ldg(&post_kernel[h * 4096 + f * 32 + d2]);
        int ks = f >> 3, kin = f & 7, tig = kin & 3, jj = kin >> 2;
        int nt = d2 >> 3, g = d2 & 7;
        int idx = ((((h * 16 + ks) * 4 + nt) * 32) + (g * 4 + tig)) * 2 + jj;
        g_Pf[idx] = tf32r(val);
    }
}

// ---------------------------------------------------------------------------
// Node kernel: 32 nodes per block, 256 threads, 2 blocks/SM.
// Stage A runs in two N-halves with one-step B-fragment double buffering;
// each half's epilogue does the fused RMS norm for its head column.
// ---------------------------------------------------------------------------
__global__ __launch_bounds__(256) void node_kernel(
    const float* __restrict__ x,
    const int*   __restrict__ deg,
    const float* __restrict__ emb_deg,
    const float* __restrict__ act_bias,
    float*       __restrict__ out)
{
    extern __shared__ float sm[];
    float* A_s   = sm;                    // [32][292]
    float* u_s   = sm + 32 * 292;         // [32][260]
    float* v_s   = u_s + 32 * 260;        // [32][260]
    float* avv_s = A_s;                   // 2 x [32][132]

    const int tid  = threadIdx.x;
    const int nb   = blockIdx.x * MTILE;
    const int lane = tid & 31, wid = tid >> 5;
    const int g = lane >> 2, t = lane & 3;

    // --- stage inputs (tf32-rounded): raw agg | t2 ---
    {
        const int n  = tid >> 3;
        const int c0 = (tid & 7) * 4;
        const int gcl = min(nb + n, N_NODES - 1);
        const float idg = (float)__ldg(&g_indeg[gcl]);
        const float* ra = g_aggx + (size_t)gcl * WIDTH;
        const float* rx = x + (size_t)gcl * WIDTH;
#pragma unroll
        for (int it = 0; it < 8; it++) {
            int c = c0 + it * 32;
            float4 a  = *(const float4*)(ra + c);
            float4 xv = __ldg((const float4*)(rx + c));
            A_s[n * 292 + c + 0] = tf32r(a.x + idg * xv.x);
            A_s[n * 292 + c + 1] = tf32r(a.y + idg * xv.y);
            A_s[n * 292 + c + 2] = tf32r(a.z + idg * xv.z);
            A_s[n * 292 + c + 3] = tf32r(a.w + idg * xv.w);
        }
        float4 t2v = *(const float4*)(g_t2 + (size_t)gcl * 32 + c0);
        A_s[n * 292 + 256 + c0 + 0] = tf32r(t2v.x);
        A_s[n * 292 + 256 + c0 + 1] = tf32r(t2v.y);
        A_s[n * 292 + 256 + c0 + 2] = tf32r(t2v.z);
        A_s[n * 292 + 256 + c0 + 3] = tf32r(t2v.w);
    }
    __syncthreads();

    // --- Stage A: [32x288] @ W2[288x512] -> U|V, fused RMS, B prefetch ---
    {
        const int wn = wid;                // 0..7, 64 cols each
        const unsigned* Au = (const unsigned*)A_s;
        const bool isU = (wn < 4);
        float* dst = isU ? u_s : v_s;
        const int cb = (wn & 3) * 64;
        const float inv_s2 = 0.70710678118654752440f;

        // deg offsets (used by U epilogue), hoisted
        int dgA0 = 0, dgB0 = 0, dgA1 = 0, dgB1 = 0;
        if (isU) {
            dgA0 = __ldg(&deg[min(nb + g,      N_NODES - 1)]) * 256;
            dgB0 = __ldg(&deg[min(nb + g +  8, N_NODES - 1)]) * 256;
            dgA1 = __ldg(&deg[min(nb + g + 16, N_NODES - 1)]) * 256;
            dgB1 = __ldg(&deg[min(nb + g + 24, N_NODES - 1)]) * 256;
        }

#pragma unroll
        for (int half = 0; half < 2; half++) {
            float4 acc[2][4];
#pragma unroll
            for (int mf = 0; mf < 2; mf++)
#pragma unroll
                for (int j = 0; j < 4; j++)
                    acc[mf][j] = make_float4(0.f, 0.f, 0.f, 0.f);

            const uint2* Bbase = ((const uint2*)g_W2f) +
                                 (wn * 8 + half * 4) * 32 + lane;
            uint2 bbn[4];
#pragma unroll
            for (int j = 0; j < 4; j++) bbn[j] = __ldg(Bbase + j * 32);

#pragma unroll 4
            for (int ks = 0; ks < 36; ks++) {
                uint2 bb[4];
#pragma unroll
                for (int j = 0; j < 4; j++) bb[j] = bbn[j];
                if (ks < 35) {
                    const uint2* Bn = Bbase + (ks + 1) * (64 * 32);
#pragma unroll
                    for (int j = 0; j < 4; j++) bbn[j] = __ldg(Bn + j * 32);
                }
                int kc = ks * 8 + t;
                unsigned a0[2], a1[2], a2[2], a3[2];
#pragma unroll
                for (int mf = 0; mf < 2; mf++) {
                    int r = (mf * 16 + g) * 292;
                    a0[mf] = Au[r + kc];
                    a1[mf] = Au[r + 2336 + kc];        // +8 rows
                    a2[mf] = Au[r + kc + 4];
                    a3[mf] = Au[r + 2336 + kc + 4];
                }
#pragma unroll
                for (int j = 0; j < 4; j++)
#pragma unroll
                    for (int mf = 0; mf < 2; mf++)
                        mma_tf32(acc[mf][j], a0[mf], a1[mf], a2[mf], a3[mf],
                                 bb[j].x, bb[j].y);
            }

            // fused RMS epilogue for this half (head column hh = half)
#pragma unroll
            for (int mf = 0; mf < 2; mf++) {
                const int rA = mf * 16 + g;
                const int rB = rA + 8;
                const int dgA = mf ? dgA1 : dgA0;
                const int dgB = mf ? dgB1 : dgB0;
                float sA = 0.f, sB = 0.f;
#pragma unroll
                for (int j = 0; j < 4; j++) {
                    float4 a = acc[mf][j];
                    sA += a.x * a.x + a.y * a.y;
                    sB += a.z * a.z + a.w * a.w;
                }
                sA += __shfl_xor_sync(0xffffffffu, sA, 1);
                sA += __shfl_xor_sync(0xffffffffu, sA, 2);
                sB += __shfl_xor_sync(0xffffffffu, sB, 1);
                sB += __shfl_xor_sync(0xffffffffu, sB, 2);
                float rinvA = rsqrtf(sA * (1.f / 32.f) + 1e-6f);
                float rinvB = rsqrtf(sB * (1.f / 32.f) + 1e-6f);
#pragma unroll
                for (int j = 0; j < 4; j++) {
                    float4 a = acc[mf][j];
                    int c = cb + (half * 4 + j) * 8 + 2 * t;
                    if (isU) {
                        float2 bA = __ldg((const float2*)(emb_deg + dgA + c));
                        float2 bB = __ldg((const float2*)(emb_deg + dgB + c));
                        *(float2*)&dst[rA * 260 + c] = make_float2(
                            tf32r((a.x * rinvA + bA.x) * inv_s2),
                            tf32r((a.y * rinvA + bA.y) * inv_s2));
                        *(float2*)&dst[rB * 260 + c] = make_float2(
                            tf32r((a.z * rinvB + bB.x) * inv_s2),
                            tf32r((a.w * rinvB + bB.y) * inv_s2));
                    } else {
                        *(float2*)&dst[rA * 260 + c] = make_float2(
                            tf32r(a.x * rinvA), tf32r(a.y * rinvA));
                        *(float2*)&dst[rB * 260 + c] = make_float2(
                            tf32r(a.z * rinvB), tf32r(a.w * rinvB));
                    }
                }
            }
        }
    }
    __syncthreads();

    const float CLIP_LO = 0.22360679774997896f;
    const float CLIP_HI = 4.47213595499957939f;
    const unsigned* U32 = (const unsigned*)u_s;
    const unsigned* V32 = (const unsigned*)v_s;

#pragma unroll 1
    for (int hp = 0; hp < 4; hp++) {
        // --- Stage B: 8 warps = 2 heads x 4 Nquarter ---
        {
            const int sub = wid >> 2;
            const int nq  = wid & 3;
            const int h   = hp * 2 + sub;
            float* avv = avv_s + sub * (32 * 132);

            float4 ag[2][4], av4[2][4];
#pragma unroll
            for (int mf = 0; mf < 2; mf++)
#pragma unroll
                for (int j = 0; j < 4; j++) {
                    ag[mf][j]  = make_float4(0.f, 0.f, 0.f, 0.f);
                    av4[mf][j] = make_float4(0.f, 0.f, 0.f, 0.f);
                }
#pragma unroll
            for (int ks = 0; ks < 4; ks++) {
                int col = h * 32 + ks * 8 + t;
                unsigned ua0[2], ua1[2], ua2[2], ua3[2];
                unsigned va0[2], va1[2], va2[2], va3[2];
#pragma unroll
                for (int mf = 0; mf < 2; mf++) {
                    int r = (mf * 16 + g) * 260;
                    ua0[mf] = U32[r + col];        ua1[mf] = U32[r + 2080 + col];
                    ua2[mf] = U32[r + col + 4];    ua3[mf] = U32[r + 2080 + col + 4];
                    va0[mf] = V32[r + col];        va1[mf] = V32[r + 2080 + col];
                    va2[mf] = V32[r + col + 4];    va3[mf] = V32[r + 2080 + col + 4];
                }
#pragma unroll
                for (int j = 0; j < 4; j++) {
                    int nt16 = nq * 4 + j;
                    uint2 bg = __ldg(((const uint2*)g_GVf) +
                                     ((h * 4 + ks) * 16 + nt16) * 32 + lane);
                    uint2 bv = __ldg(((const uint2*)g_GVf) +
                                     (((8 + h) * 4 + ks) * 16 + nt16) * 32 + lane);
#pragma unroll
                    for (int mf = 0; mf < 2; mf++) {
                        mma_tf32(ag[mf][j],  ua0[mf], ua1[mf], ua2[mf], ua3[mf], bg.x, bg.y);
                        mma_tf32(av4[mf][j], va0[mf], va1[mf], va2[mf], va3[mf], bv.x, bv.y);
                    }
                }
            }
#pragma unroll
            for (int j = 0; j < 4; j++) {
                int c = nq * 32 + j * 8 + 2 * t;
                float2 bias = __ldg((const float2*)(act_bias + h * 128 + c));
#pragma unroll
                for (int mf = 0; mf < 2; mf++) {
                    int r = (mf * 16 + g) * 132;
                    float o0 = fminf(fmaxf(sp(ag[mf][j].x + bias.x), CLIP_LO), CLIP_HI) * av4[mf][j].x;
                    float o1 = fminf(fmaxf(sp(ag[mf][j].y + bias.y), CLIP_LO), CLIP_HI) * av4[mf][j].y;
                    float o2 = fminf(fmaxf(sp(ag[mf][j].z + bias.x), CLIP_LO), CLIP_HI) * av4[mf][j].z;
                    float o3 = fminf(fmaxf(sp(ag[mf][j].w + bias.y), CLIP_LO), CLIP_HI) * av4[mf][j].w;
                    avv[r + c + 0]        = tf32r(o0);
                    avv[r + c + 1]        = tf32r(o1);
                    avv[r + 1056 + c + 0] = tf32r(o2);
                    avv[r + 1056 + c + 1] = tf32r(o3);
                }
            }
        }
        __syncthreads();

        // --- Stage D: 8 warps = 2 heads x 4 col8 (2 rotating accs per mf) ---
        {
            const int sub = wid >> 2;
            const int c8  = wid & 3;
            const int h   = hp * 2 + sub;
            const unsigned* AV = (const unsigned*)(avv_s + sub * (32 * 132));
            float4 dacc[2][2];
#pragma unroll
            for (int mf = 0; mf < 2; mf++) {
                dacc[mf][0] = make_float4(0.f, 0.f, 0.f, 0.f);
                dacc[mf][1] = make_float4(0.f, 0.f, 0.f, 0.f);
            }
#pragma unroll
            for (int ks = 0; ks < 16; ks++) {
                int kc = ks * 8 + t;
                uint2 bb = __ldg(((const uint2*)g_Pf) +
                                 ((h * 16 + ks) * 4 + c8) * 32 + lane);
#pragma unroll
                for (int mf = 0; mf < 2; mf++) {
                    int r = (mf * 16 + g) * 132;
                    mma_tf32(dacc[mf][ks & 1], AV[r + kc], AV[r + 1056 + kc],
                             AV[r + kc + 4], AV[r + 1056 + kc + 4], bb.x, bb.y);
                }
            }
            int col = h * 32 + c8 * 8 + 2 * t;
#pragma unroll
            for (int mf = 0; mf < 2; mf++) {
                float4 d0 = dacc[mf][0], d1 = dacc[mf][1];
                float4 s = make_float4(d0.x + d1.x, d0.y + d1.y,
                                       d0.z + d1.z, d0.w + d1.w);
                int row0 = nb + mf * 16 + g;
                if (row0 < N_NODES)
                    *(float2*)&out[(size_t)row0 * WIDTH + col] =
                        make_float2(s.x, s.y);
                if (row0 + 8 < N_NODES)
                    *(float2*)&out[(size_t)(row0 + 8) * WIDTH + col] =
                        make_float2(s.z, s.w);
            }
        }
        __syncthreads();
    }
}

// ---------------------------------------------------------------------------
// Launch
// ---------------------------------------------------------------------------
extern "C" void kernel_launch(void* const* d_in, const int* in_sizes, int n_in,
                              void* d_out, int out_size) {
    const float* x            = (const float*)d_in[0];
    const int*   deg          = (const int*)  d_in[1];
    const int*   edge_idx     = (const int*)  d_in[2];
    const int*   edge_attr    = (const int*)  d_in[3];
    const float* node_elec    = (const float*)d_in[4];
    const float* lora_down    = (const float*)d_in[5];
    const float* lora_up      = (const float*)d_in[6];
    const float* emb_edge     = (const float*)d_in[7];
    const float* moa_w        = (const float*)d_in[8];
    const float* moa_s        = (const float*)d_in[9];
    const float* elec_lin     = (const float*)d_in[10];
    const float* emb_deg      = (const float*)d_in[11];
    const float* lin_pre      = (const float*)d_in[12];
    const float* gate_lin     = (const float*)d_in[13];
    const float* gate_kernel  = (const float*)d_in[14];
    const float* value_lin    = (const float*)d_in[15];
    const float* value_kernel = (const float*)d_in[16];
    const float* act_bias     = (const float*)d_in[17];
    const float* post_kernel  = (const float*)d_in[18];
    float* out = (float*)d_out;

    size_t ism = (size_t)32 * 260 * sizeof(float);   // 33280 B
    init_kernel<<<1875 + 1024, 256, ism>>>(x, lora_down);

    work_kernel<<<8028, 256>>>(
        x, edge_idx, edge_attr, node_elec,
        emb_edge, moa_w, moa_s, elec_lin,
        lin_pre, lora_up, gate_lin, value_lin,
        gate_kernel, value_kernel, post_kernel);

    size_t nsm = ((size_t)32 * 292 + 2 * 32 * 260) * sizeof(float);  // 103936 B
    cudaFuncSetAttribute(node_kernel,
                         cudaFuncAttributeMaxDynamicSharedMemorySize, (int)nsm);
    node_kernel<<<(N_NODES + MTILE - 1) / MTILE, 256, nsm>>>(
        x, deg, emb_deg, act_bias, out);
}

// round 14
// speedup vs baseline: 1.0470x; 1.0470x over previous
#include <cuda_runtime.h>
#include <cstddef>

#define N_NODES   60000
#define N_EDGES   240000
#define WIDTH     256
#define DIM_HEAD  32
#define NUM_HEAD  8
#define MTILE     32

// ---------------------------------------------------------------------------
// Device scratch
// ---------------------------------------------------------------------------
__device__ float g_aggx[(size_t)N_NODES * WIDTH];     // segment_sum(x[i0])
__device__ float g_t2  [(size_t)N_NODES * DIM_HEAD];  // segment_sum(t2)
__device__ int   g_indeg[N_NODES];
__device__ float g_xld [(size_t)N_NODES * DIM_HEAD];  // x @ lora_down

// mma-B-fragment swizzled weights (tf32-rounded fp32 bit patterns)
__device__ float g_W2f[36 * 64 * 32 * 2];          // W2 288x512: [ks][col8][lane][2]
__device__ float g_GVf[2 * 8 * 4 * 16 * 32 * 2];   // gate/value kernels
__device__ float g_Pf [8 * 16 * 4 * 32 * 2];       // post kernel

__device__ __forceinline__ float sp(float x) {
    return fmaxf(x, 0.f) + log1pf(expf(-fabsf(x)));
}
__device__ __forceinline__ float wsum(float v) {
#pragma unroll
    for (int o = 16; o; o >>= 1) v += __shfl_xor_sync(0xffffffffu, v, o);
    return v;
}
__device__ __forceinline__ void red_add_v4(float* p, float4 v) {
    asm volatile("red.global.add.v4.f32 [%0], {%1, %2, %3, %4};"
                 :: "l"(p), "f"(v.x), "f"(v.y), "f"(v.z), "f"(v.w)
                 : "memory");
}
__device__ __forceinline__ float tf32r(float f) {
    unsigned r;
    asm("cvt.rna.tf32.f32 %0, %1;" : "=r"(r) : "f"(f));
    return __uint_as_float(r);
}
__device__ __forceinline__ void mma_tf32(float4& c,
    unsigned a0, unsigned a1, unsigned a2, unsigned a3,
    unsigned b0, unsigned b1)
{
    asm volatile(
        "mma.sync.aligned.m16n8k8.row.col.f32.tf32.tf32.f32 "
        "{%0,%1,%2,%3},{%4,%5,%6,%7},{%8,%9},{%0,%1,%2,%3};"
        : "+f"(c.x), "+f"(c.y), "+f"(c.z), "+f"(c.w)
        : "r"(a0), "r"(a1), "r"(a2), "r"(a3), "r"(b0), "r"(b1));
}

// ---------------------------------------------------------------------------
// init_kernel: blocks [0,1875) xld via mma (rotating accs + B prefetch);
//              blocks [1875,2899) zero g_aggx/g_t2/g_indeg.
// ---------------------------------------------------------------------------
__global__ __launch_bounds__(256) void init_kernel(
    const float* __restrict__ x,
    const float* __restrict__ lora_down)
{
    const int b = blockIdx.x, tid = threadIdx.x;
    if (b < 1875) {
        extern __shared__ float xs[];      // [32][260]
        const int nb = b * 32;
        const int lane = tid & 31, wid = tid >> 5;
        const int g = lane >> 2, t = lane & 3;
        {
            const int n  = tid >> 3;
            const int c0 = (tid & 7) * 4;
            const int gcl = min(nb + n, N_NODES - 1);
            const float* xr = x + (size_t)gcl * WIDTH;
#pragma unroll
            for (int it = 0; it < 8; it++) {
                int c = c0 + it * 32;
                float4 v = __ldg((const float4*)(xr + c));
                xs[n * 260 + c + 0] = tf32r(v.x);
                xs[n * 260 + c + 1] = tf32r(v.y);
                xs[n * 260 + c + 2] = tf32r(v.z);
                xs[n * 260 + c + 3] = tf32r(v.w);
            }
        }
        __syncthreads();
        const int wm = wid >> 2, wn = wid & 3;   // 2 M x 4 N
        const unsigned* Xu = (const unsigned*)xs;
        const int r = (wm * 16 + g) * 260;
        const int bcol = wn * 8 + g;
        float4 acc[4];
#pragma unroll
        for (int q = 0; q < 4; q++) acc[q] = make_float4(0.f, 0.f, 0.f, 0.f);

        float bp0 = __ldg(&lora_down[t * 32 + bcol]);
        float bp1 = __ldg(&lora_down[(4 + t) * 32 + bcol]);
#pragma unroll 4
        for (int ks = 0; ks < 32; ks++) {
            unsigned b0 = __float_as_uint(tf32r(bp0));
            unsigned b1 = __float_as_uint(tf32r(bp1));
            if (ks < 31) {
                bp0 = __ldg(&lora_down[((ks + 1) * 8 + t) * 32 + bcol]);
                bp1 = __ldg(&lora_down[((ks + 1) * 8 + 4 + t) * 32 + bcol]);
            }
            int kc = ks * 8 + t;
            unsigned a0 = Xu[r + kc];
            unsigned a1 = Xu[r + 2080 + kc];
            unsigned a2 = Xu[r + kc + 4];
            unsigned a3 = Xu[r + 2080 + kc + 4];
            mma_tf32(acc[ks & 3], a0, a1, a2, a3, b0, b1);
        }
        float4 s;
        s.x = (acc[0].x + acc[1].x) + (acc[2].x + acc[3].x);
        s.y = (acc[0].y + acc[1].y) + (acc[2].y + acc[3].y);
        s.z = (acc[0].z + acc[1].z) + (acc[2].z + acc[3].z);
        s.w = (acc[0].w + acc[1].w) + (acc[2].w + acc[3].w);
        int col = wn * 8 + 2 * t;
        int row0 = nb + wm * 16 + g;
        if (row0 < N_NODES)
            *(float2*)&g_xld[(size_t)row0 * 32 + col] = make_float2(s.x, s.y);
        if (row0 + 8 < N_NODES)
            *(float2*)&g_xld[(size_t)(row0 + 8) * 32 + col] = make_float2(s.z, s.w);
    } else {
        size_t i0 = (size_t)(b - 1875) * 256 + tid;
        size_t step = (size_t)1024 * 256;
        size_t n4 = (size_t)N_NODES * WIDTH / 4;
        float4* p = (float4*)g_aggx;
        for (size_t i = i0; i < n4; i += step)
            p[i] = make_float4(0.f, 0.f, 0.f, 0.f);
        size_t m4 = (size_t)N_NODES * DIM_HEAD / 4;
        float4* q4 = (float4*)g_t2;
        for (size_t i = i0; i < m4; i += step)
            q4[i] = make_float4(0.f, 0.f, 0.f, 0.f);
        for (size_t i = i0; i < N_NODES; i += step)
            g_indeg[i] = 0;
    }
}

// ---------------------------------------------------------------------------
// work_kernel: blocks [0,7500) edge ; [7500,7644) W2 gemm+swizzle ;
// [7644,7900) gate/value swizzle ; [7900,8028) post swizzle.
// ---------------------------------------------------------------------------
__global__ __launch_bounds__(256) void work_kernel(
    const float* __restrict__ x,
    const int*   __restrict__ edge_idx,
    const int*   __restrict__ edge_attr,
    const float* __restrict__ node_elec,
    const float* __restrict__ emb_edge,
    const float* __restrict__ moa_w,
    const float* __restrict__ moa_s,
    const float* __restrict__ elec_lin,
    const float* __restrict__ lin_pre,
    const float* __restrict__ lora_up,
    const float* __restrict__ gate_lin,
    const float* __restrict__ value_lin,
    const float* __restrict__ gate_kernel,
    const float* __restrict__ value_kernel,
    const float* __restrict__ post_kernel)
{
    __shared__ int   s_i0[32], s_i1[32];
    __shared__ float emb_s[32][33];

    const int b = blockIdx.x, tid = threadIdx.x;

    if (b < 7500) {
        const int eb = b * 32;
        if (tid < 32) {
            int i0 = edge_idx[eb + tid];
            int i1 = edge_idx[N_EDGES + eb + tid];
            s_i0[tid] = i0;
            s_i1[tid] = i1;
            atomicAdd(&g_indeg[i1], 1);
        }
        __syncthreads();
        {
            const int wid = tid >> 5, lane = tid & 31;
            float w0 = sp(moa_w[lane]);
            float w1 = sp(moa_w[32 + lane]);
            w0 /= wsum(w0);
            w1 /= wsum(w1);
            const float s0  = sp(moa_s[lane]);
            const float s1  = sp(moa_s[32 + lane]);
            const float el0 = elec_lin[lane];
            const float el1 = elec_lin[32 + lane];
#pragma unroll
            for (int i = 0; i < 4; i++) {
                int e  = wid * 4 + i;
                int i0 = s_i0[e], i1 = s_i1[e];
                float d0 = node_elec[2 * i0]     - node_elec[2 * i1];
                float d1 = node_elec[2 * i0 + 1] - node_elec[2 * i1 + 1];
                float m0 = wsum(tanhf(d0 * s0) * w0);
                float m1 = wsum(tanhf(d1 * s1) * w1);
                int ge = eb + e;
                int a0 = edge_attr[3 * ge], a1 = edge_attr[3 * ge + 1],
                    a2 = edge_attr[3 * ge + 2];
                emb_s[e][lane] = emb_edge[a0 * 32 + lane] + emb_edge[a1 * 32 + lane] +
                                 emb_edge[a2 * 32 + lane] + m0 * el0 + m1 * el1;
            }
        }
        __syncthreads();

        const int e  = tid >> 3;
        const int i0 = s_i0[e], i1 = s_i1[e];
        {
            const int d = (tid & 7) * 4;
            float4 a = __ldg((const float4*)(g_xld + (size_t)i0 * 32 + d));
            float4 bb = __ldg((const float4*)(g_xld + (size_t)i1 * 32 + d));
            float4 t;
            t.x = (a.x + bb.x) * emb_s[e][d + 0];
            t.y = (a.y + bb.y) * emb_s[e][d + 1];
            t.z = (a.z + bb.z) * emb_s[e][d + 2];
            t.w = (a.w + bb.w) * emb_s[e][d + 3];
            red_add_v4(g_t2 + (size_t)i1 * 32 + d, t);
        }
        {
            const int c0 = (tid & 7) * 4;
            const float4* xr = (const float4*)(x + (size_t)i0 * WIDTH);
            float* dst = g_aggx + (size_t)i1 * WIDTH;
#pragma unroll
            for (int it = 0; it < 8; it++) {
                int c = c0 + it * 32;
                float4 v = __ldg(&xr[c >> 2]);
                red_add_v4(dst + c, v);
            }
        }
    } else if (b < 7644) {
        int id = (b - 7500) * 256 + tid;   // 36864
        int k  = id >> 7;                  // 0..287
        int n  = (id & 127) * 4;           // 0..508
        const float* srow = (k < 256) ? (lin_pre + k * 256)
                                      : (lora_up + (k - 256) * 256);
        const float* M = (n < 256) ? gate_lin : value_lin;
        int nn = n & 255;
        float4 acc = make_float4(0.f, 0.f, 0.f, 0.f);
#pragma unroll 4
        for (int j = 0; j < 256; j++) {
            float  s = __ldg(&srow[j]);
            float4 m = __ldg((const float4*)(M + j * 256 + nn));
            acc.x += s * m.x; acc.y += s * m.y;
            acc.z += s * m.z; acc.w += s * m.w;
        }
        int ks = k >> 3, kin = k & 7, tig = kin & 3, jj = kin >> 2;
        float v[4] = {acc.x, acc.y, acc.z, acc.w};
#pragma unroll
        for (int q = 0; q < 4; q++) {
            int nq = n + q;
            int idx = ((ks * 64 + (nq >> 3)) * 32 + ((nq & 7) * 4 + tig)) * 2 + jj;
            g_W2f[idx] = tf32r(v[q]);
        }
    } else if (b < 7900) {
        int id = (b - 7644) * 256 + tid;   // 65536
        int path = id >> 15;
        int h    = (id >> 12) & 7;
        int d    = (id >> 7) & 31;
        int f    = id & 127;
        float val = path ? __ldg(&value_kernel[h * 4096 + d * 128 + f])
                         : __ldg(&gate_kernel [h * 4096 + d * 128 + f]);
        int ks = d >> 3, kin = d & 7, tig = kin & 3, jj = kin >> 2;
        int nt = f >> 3, g = f & 7;
        int idx = (((((path * 8 + h) * 4 + ks) * 16 + nt) * 32) + (g * 4 + tig)) * 2 + jj;
        g_GVf[idx] = tf32r(val);
    } else {
        int p = (b - 7900) * 256 + tid;    // 32768
        int h = p >> 12;
        int f = (p >> 5) & 127;
        int d2 = p & 31;
        float val = __ldg(&post_kernel[h * 4096 + f * 32 + d2]);
        int ks = f >> 3, kin = f & 7, tig = kin & 3, jj = kin >> 2;
        int nt = d2 >> 3, g = d2 & 7;
        int idx = ((((h * 16 + ks) * 4 + nt) * 32) + (g * 4 + tig)) * 2 + jj;
        g_Pf[idx] = tf32r(val);
    }
}

// ---------------------------------------------------------------------------
// Node kernel: 32 nodes per block, 256 threads, 2 blocks/SM.
// (round-12 structure; stage A unroll widened to 6)
// ---------------------------------------------------------------------------
__global__ __launch_bounds__(256) void node_kernel(
    const float* __restrict__ x,
    const int*   __restrict__ deg,
    const float* __restrict__ emb_deg,
    const float* __restrict__ act_bias,
    float*       __restrict__ out)
{
    extern __shared__ float sm[];
    float* A_s   = sm;                    // [32][292]
    float* u_s   = sm + 32 * 292;         // [32][260]
    float* v_s   = u_s + 32 * 260;        // [32][260]
    float* avv_s = A_s;                   // 2 x [32][132]

    const int tid  = threadIdx.x;
    const int nb   = blockIdx.x * MTILE;
    const int lane = tid & 31, wid = tid >> 5;
    const int g = lane >> 2, t = lane & 3;

    // --- stage inputs (tf32-rounded): raw agg | t2 ---
    {
        const int n  = tid >> 3;
        const int c0 = (tid & 7) * 4;
        const int gcl = min(nb + n, N_NODES - 1);
        const float idg = (float)__ldg(&g_indeg[gcl]);
        const float* ra = g_aggx + (size_t)gcl * WIDTH;
        const float* rx = x + (size_t)gcl * WIDTH;
#pragma unroll
        for (int it = 0; it < 8; it++) {
            int c = c0 + it * 32;
            float4 a  = *(const float4*)(ra + c);
            float4 xv = __ldg((const float4*)(rx + c));
            A_s[n * 292 + c + 0] = tf32r(a.x + idg * xv.x);
            A_s[n * 292 + c + 1] = tf32r(a.y + idg * xv.y);
            A_s[n * 292 + c + 2] = tf32r(a.z + idg * xv.z);
            A_s[n * 292 + c + 3] = tf32r(a.w + idg * xv.w);
        }
        float4 t2v = *(const float4*)(g_t2 + (size_t)gcl * 32 + c0);
        A_s[n * 292 + 256 + c0 + 0] = tf32r(t2v.x);
        A_s[n * 292 + 256 + c0 + 1] = tf32r(t2v.y);
        A_s[n * 292 + 256 + c0 + 2] = tf32r(t2v.z);
        A_s[n * 292 + 256 + c0 + 3] = tf32r(t2v.w);
    }
    __syncthreads();

    // --- Stage A: [32x288] @ W2[288x512] -> U|V with fused RMS norm ---
    {
        const int wn = wid;                // 0..7, 64 cols each
        const unsigned* Au = (const unsigned*)A_s;
        float4 acc[2][8];
#pragma unroll
        for (int mf = 0; mf < 2; mf++)
#pragma unroll
            for (int nt = 0; nt < 8; nt++)
                acc[mf][nt] = make_float4(0.f, 0.f, 0.f, 0.f);

        const uint2* Bp = ((const uint2*)g_W2f) + (wn * 8) * 32 + lane;
#pragma unroll 6
        for (int ks = 0; ks < 36; ks++) {
            int kc = ks * 8 + t;
            unsigned a0[2], a1[2], a2[2], a3[2];
#pragma unroll
            for (int mf = 0; mf < 2; mf++) {
                int r = (mf * 16 + g) * 292;
                a0[mf] = Au[r + kc];
                a1[mf] = Au[r + 2336 + kc];        // +8 rows
                a2[mf] = Au[r + kc + 4];
                a3[mf] = Au[r + 2336 + kc + 4];
            }
            const uint2* Bks = Bp + ks * 64 * 32;
#pragma unroll
            for (int nt = 0; nt < 8; nt++) {
                uint2 bb = __ldg(Bks + nt * 32);
#pragma unroll
                for (int mf = 0; mf < 2; mf++)
                    mma_tf32(acc[mf][nt], a0[mf], a1[mf], a2[mf], a3[mf], bb.x, bb.y);
            }
        }

        // fused RMS epilogue: cols of one head live in lanes g*4+{0..3}
        const bool isU = (wn < 4);
        float* dst = isU ? u_s : v_s;
        const int cb = (wn & 3) * 64;
        const float inv_s2 = 0.70710678118654752440f;
#pragma unroll
        for (int mf = 0; mf < 2; mf++) {
            const int rA = mf * 16 + g;
            const int rB = rA + 8;
            int dgA = 0, dgB = 0;
            if (isU) {
                dgA = __ldg(&deg[min(nb + rA, N_NODES - 1)]) * 256;
                dgB = __ldg(&deg[min(nb + rB, N_NODES - 1)]) * 256;
            }
#pragma unroll
            for (int hh = 0; hh < 2; hh++) {
                float sA = 0.f, sB = 0.f;
#pragma unroll
                for (int j = 0; j < 4; j++) {
                    float4 a = acc[mf][hh * 4 + j];
                    sA += a.x * a.x + a.y * a.y;
                    sB += a.z * a.z + a.w * a.w;
                }
                sA += __shfl_xor_sync(0xffffffffu, sA, 1);
                sA += __shfl_xor_sync(0xffffffffu, sA, 2);
                sB += __shfl_xor_sync(0xffffffffu, sB, 1);
                sB += __shfl_xor_sync(0xffffffffu, sB, 2);
                float rinvA = rsqrtf(sA * (1.f / 32.f) + 1e-6f);
                float rinvB = rsqrtf(sB * (1.f / 32.f) + 1e-6f);
#pragma unroll
                for (int j = 0; j < 4; j++) {
                    float4 a = acc[mf][hh * 4 + j];
                    int c = cb + (hh * 4 + j) * 8 + 2 * t;
                    if (isU) {
                        float2 bA = __ldg((const float2*)(emb_deg + dgA + c));
                        float2 bB = __ldg((const float2*)(emb_deg + dgB + c));
                        *(float2*)&dst[rA * 260 + c] = make_float2(
                            tf32r((a.x * rinvA + bA.x) * inv_s2),
                            tf32r((a.y * rinvA + bA.y) * inv_s2));
                        *(float2*)&dst[rB * 260 + c] = make_float2(
                            tf32r((a.z * rinvB + bB.x) * inv_s2),
                            tf32r((a.w * rinvB + bB.y) * inv_s2));
                    } else {
                        *(float2*)&dst[rA * 260 + c] = make_float2(
                            tf32r(a.x * rinvA), tf32r(a.y * rinvA));
                        *(float2*)&dst[rB * 260 + c] = make_float2(
                            tf32r(a.z * rinvB), tf32r(a.w * rinvB));
                    }
                }
            }
        }
    }
    __syncthreads();

    const float CLIP_LO = 0.22360679774997896f;
    const float CLIP_HI = 4.47213595499957939f;
    const unsigned* U32 = (const unsigned*)u_s;
    const unsigned* V32 = (const unsigned*)v_s;

#pragma unroll 1
    for (int hp = 0; hp < 4; hp++) {
        // --- Stage B: 8 warps = 2 heads x 4 Nquarter ---
        {
            const int sub = wid >> 2;
            const int nq  = wid & 3;
            const int h   = hp * 2 + sub;
            float* avv = avv_s + sub * (32 * 132);

            float4 ag[2][4], av4[2][4];
#pragma unroll
            for (int mf = 0; mf < 2; mf++)
#pragma unroll
                for (int j = 0; j < 4; j++) {
                    ag[mf][j]  = make_float4(0.f, 0.f, 0.f, 0.f);
                    av4[mf][j] = make_float4(0.f, 0.f, 0.f, 0.f);
                }
#pragma unroll
            for (int ks = 0; ks < 4; ks++) {
                int col = h * 32 + ks * 8 + t;
                unsigned ua0[2], ua1[2], ua2[2], ua3[2];
                unsigned va0[2], va1[2], va2[2], va3[2];
#pragma unroll
                for (int mf = 0; mf < 2; mf++) {
                    int r = (mf * 16 + g) * 260;
                    ua0[mf] = U32[r + col];        ua1[mf] = U32[r + 2080 + col];
                    ua2[mf] = U32[r + col + 4];    ua3[mf] = U32[r + 2080 + col + 4];
                    va0[mf] = V32[r + col];        va1[mf] = V32[r + 2080 + col];
                    va2[mf] = V32[r + col + 4];    va3[mf] = V32[r + 2080 + col + 4];
                }
#pragma unroll
                for (int j = 0; j < 4; j++) {
                    int nt16 = nq * 4 + j;
                    uint2 bg = __ldg(((const uint2*)g_GVf) +
                                     ((h * 4 + ks) * 16 + nt16) * 32 + lane);
                    uint2 bv = __ldg(((const uint2*)g_GVf) +
                                     (((8 + h) * 4 + ks) * 16 + nt16) * 32 + lane);
#pragma unroll
                    for (int mf = 0; mf < 2; mf++) {
                        mma_tf32(ag[mf][j],  ua0[mf], ua1[mf], ua2[mf], ua3[mf], bg.x, bg.y);
                        mma_tf32(av4[mf][j], va0[mf], va1[mf], va2[mf], va3[mf], bv.x, bv.y);
                    }
                }
            }
#pragma unroll
            for (int j = 0; j < 4; j++) {
                int c = nq * 32 + j * 8 + 2 * t;
                float2 bias = __ldg((const float2*)(act_bias + h * 128 + c));
#pragma unroll
                for (int mf = 0; mf < 2; mf++) {
                    int r = (mf * 16 + g) * 132;
                    float o0 = fminf(fmaxf(sp(ag[mf][j].x + bias.x), CLIP_LO), CLIP_HI) * av4[mf][j].x;
                    float o1 = fminf(fmaxf(sp(ag[mf][j].y + bias.y), CLIP_LO), CLIP_HI) * av4[mf][j].y;
                    float o2 = fminf(fmaxf(sp(ag[mf][j].z + bias.x), CLIP_LO), CLIP_HI) * av4[mf][j].z;
                    float o3 = fminf(fmaxf(sp(ag[mf][j].w + bias.y), CLIP_LO), CLIP_HI) * av4[mf][j].w;
                    avv[r + c + 0]        = tf32r(o0);
                    avv[r + c + 1]        = tf32r(o1);
                    avv[r + 1056 + c + 0] = tf32r(o2);
                    avv[r + 1056 + c + 1] = tf32r(o3);
                }
            }
        }
        __syncthreads();

        // --- Stage D: 8 warps = 2 heads x 4 col8 (2 rotating accs per mf) ---
        {
            const int sub = wid >> 2;
            const int c8  = wid & 3;
            const int h   = hp * 2 + sub;
            const unsigned* AV = (const unsigned*)(avv_s + sub * (32 * 132));
            float4 dacc[2][2];
#pragma unroll
            for (int mf = 0; mf < 2; mf++) {
                dacc[mf][0] = make_float4(0.f, 0.f, 0.f, 0.f);
                dacc[mf][1] = make_float4(0.f, 0.f, 0.f, 0.f);
            }
#pragma unroll
            for (int ks = 0; ks < 16; ks++) {
                int kc = ks * 8 + t;
                uint2 bb = __ldg(((const uint2*)g_Pf) +
                                 ((h * 16 + ks) * 4 + c8) * 32 + lane);
#pragma unroll
                for (int mf = 0; mf < 2; mf++) {
                    int r = (mf * 16 + g) * 132;
                    mma_tf32(dacc[mf][ks & 1], AV[r + kc], AV[r + 1056 + kc],
                             AV[r + kc + 4], AV[r + 1056 + kc + 4], bb.x, bb.y);
                }
            }
            int col = h * 32 + c8 * 8 + 2 * t;
#pragma unroll
            for (int mf = 0; mf < 2; mf++) {
                float4 d0 = dacc[mf][0], d1 = dacc[mf][1];
                float4 s = make_float4(d0.x + d1.x, d0.y + d1.y,
                                       d0.z + d1.z, d0.w + d1.w);
                int row0 = nb + mf * 16 + g;
                if (row0 < N_NODES)
                    *(float2*)&out[(size_t)row0 * WIDTH + col] =
                        make_float2(s.x, s.y);
                if (row0 + 8 < N_NODES)
                    *(float2*)&out[(size_t)(row0 + 8) * WIDTH + col] =
                        make_float2(s.z, s.w);
            }
        }
        __syncthreads();
    }
}

// ---------------------------------------------------------------------------
// Launch
// ---------------------------------------------------------------------------
extern "C" void kernel_launch(void* const* d_in, const int* in_sizes, int n_in,
                              void* d_out, int out_size) {
    const float* x            = (const float*)d_in[0];
    const int*   deg          = (const int*)  d_in[1];
    const int*   edge_idx     = (const int*)  d_in[2];
    const int*   edge_attr    = (const int*)  d_in[3];
    const float* node_elec    = (const float*)d_in[4];
    const float* lora_down    = (const float*)d_in[5];
    const float* lora_up      = (const float*)d_in[6];
    const float* emb_edge     = (const float*)d_in[7];
    const float* moa_w        = (const float*)d_in[8];
    const float* moa_s        = (const float*)d_in[9];
    const float* elec_lin     = (const float*)d_in[10];
    const float* emb_deg      = (const float*)d_in[11];
    const float* lin_pre      = (const float*)d_in[12];
    const float* gate_lin     = (const float*)d_in[13];
    const float* gate_kernel  = (const float*)d_in[14];
    const float* value_lin    = (const float*)d_in[15];
    const float* value_kernel = (const float*)d_in[16];
    const float* act_bias     = (const float*)d_in[17];
    const float* post_kernel  = (const float*)d_in[18];
    float* out = (float*)d_out;

    size_t ism = (size_t)32 * 260 * sizeof(float);   // 33280 B
    init_kernel<<<1875 + 1024, 256, ism>>>(x, lora_down);

    work_kernel<<<8028, 256>>>(
        x, edge_idx, edge_attr, node_elec,
        emb_edge, moa_w, moa_s, elec_lin,
        lin_pre, lora_up, gate_lin, value_lin,
        gate_kernel, value_kernel, post_kernel);

    size_t nsm = ((size_t)32 * 292 + 2 * 32 * 260) * sizeof(float);  // 103936 B
    cudaFuncSetAttribute(node_kernel,
                         cudaFuncAttributeMaxDynamicSharedMemorySize, (int)nsm);
    node_kernel<<<(N_NODES + MTILE - 1) / MTILE, 256, nsm>>>(
        x, deg, emb_deg, act_bias, out);
}

// round 15
// speedup vs baseline: 1.1341x; 1.0832x over previous
#include <cuda_runtime.h>
#include <cstddef>

#define N_NODES   60000
#define N_EDGES   240000
#define WIDTH     256
#define DIM_HEAD  32
#define NUM_HEAD  8
#define MTILE     32
#define NTILES    1875
#define NODE_GRID 296

// ---------------------------------------------------------------------------
// Device scratch
// ---------------------------------------------------------------------------
__device__ float g_aggx[(size_t)N_NODES * WIDTH];     // segment_sum(x[i0])
__device__ float g_t2  [(size_t)N_NODES * DIM_HEAD];  // segment_sum(t2)
__device__ int   g_indeg[N_NODES];
__device__ float g_xld [(size_t)N_NODES * DIM_HEAD];  // x @ lora_down

// mma-B-fragment swizzled weights (tf32-rounded fp32 bit patterns)
__device__ float g_W2f[36 * 64 * 32 * 2];          // W2 288x512: [ks][col8][lane][2]
__device__ float g_GVf[2 * 8 * 4 * 16 * 32 * 2];   // gate/value kernels
__device__ float g_Pf [8 * 16 * 4 * 32 * 2];       // post kernel

__device__ __forceinline__ float sp(float x) {
    return fmaxf(x, 0.f) + log1pf(expf(-fabsf(x)));
}
__device__ __forceinline__ float wsum(float v) {
#pragma unroll
    for (int o = 16; o; o >>= 1) v += __shfl_xor_sync(0xffffffffu, v, o);
    return v;
}
__device__ __forceinline__ void red_add_v4(float* p, float4 v) {
    asm volatile("red.global.add.v4.f32 [%0], {%1, %2, %3, %4};"
                 :: "l"(p), "f"(v.x), "f"(v.y), "f"(v.z), "f"(v.w)
                 : "memory");
}
__device__ __forceinline__ float tf32r(float f) {
    unsigned r;
    asm("cvt.rna.tf32.f32 %0, %1;" : "=r"(r) : "f"(f));
    return __uint_as_float(r);
}
__device__ __forceinline__ void mma_tf32(float4& c,
    unsigned a0, unsigned a1, unsigned a2, unsigned a3,
    unsigned b0, unsigned b1)
{
    asm volatile(
        "mma.sync.aligned.m16n8k8.row.col.f32.tf32.tf32.f32 "
        "{%0,%1,%2,%3},{%4,%5,%6,%7},{%8,%9},{%0,%1,%2,%3};"
        : "+f"(c.x), "+f"(c.y), "+f"(c.z), "+f"(c.w)
        : "r"(a0), "r"(a1), "r"(a2), "r"(a3), "r"(b0), "r"(b1));
}

// ---------------------------------------------------------------------------
// init_kernel: blocks [0,1875) xld via mma (rotating accs + B prefetch);
//              blocks [1875,2899) zero g_aggx/g_t2/g_indeg.
// ---------------------------------------------------------------------------
__global__ __launch_bounds__(256) void init_kernel(
    const float* __restrict__ x,
    const float* __restrict__ lora_down)
{
    const int b = blockIdx.x, tid = threadIdx.x;
    if (b < 1875) {
        extern __shared__ float xs[];      // [32][260]
        const int nb = b * 32;
        const int lane = tid & 31, wid = tid >> 5;
        const int g = lane >> 2, t = lane & 3;
        {
            const int n  = tid >> 3;
            const int c0 = (tid & 7) * 4;
            const int gcl = min(nb + n, N_NODES - 1);
            const float* xr = x + (size_t)gcl * WIDTH;
#pragma unroll
            for (int it = 0; it < 8; it++) {
                int c = c0 + it * 32;
                float4 v = __ldg((const float4*)(xr + c));
                xs[n * 260 + c + 0] = tf32r(v.x);
                xs[n * 260 + c + 1] = tf32r(v.y);
                xs[n * 260 + c + 2] = tf32r(v.z);
                xs[n * 260 + c + 3] = tf32r(v.w);
            }
        }
        __syncthreads();
        const int wm = wid >> 2, wn = wid & 3;   // 2 M x 4 N
        const unsigned* Xu = (const unsigned*)xs;
        const int r = (wm * 16 + g) * 260;
        const int bcol = wn * 8 + g;
        float4 acc[4];
#pragma unroll
        for (int q = 0; q < 4; q++) acc[q] = make_float4(0.f, 0.f, 0.f, 0.f);

        float bp0 = __ldg(&lora_down[t * 32 + bcol]);
        float bp1 = __ldg(&lora_down[(4 + t) * 32 + bcol]);
#pragma unroll 4
        for (int ks = 0; ks < 32; ks++) {
            unsigned b0 = __float_as_uint(tf32r(bp0));
            unsigned b1 = __float_as_uint(tf32r(bp1));
            if (ks < 31) {
                bp0 = __ldg(&lora_down[((ks + 1) * 8 + t) * 32 + bcol]);
                bp1 = __ldg(&lora_down[((ks + 1) * 8 + 4 + t) * 32 + bcol]);
            }
            int kc = ks * 8 + t;
            unsigned a0 = Xu[r + kc];
            unsigned a1 = Xu[r + 2080 + kc];
            unsigned a2 = Xu[r + kc + 4];
            unsigned a3 = Xu[r + 2080 + kc + 4];
            mma_tf32(acc[ks & 3], a0, a1, a2, a3, b0, b1);
        }
        float4 s;
        s.x = (acc[0].x + acc[1].x) + (acc[2].x + acc[3].x);
        s.y = (acc[0].y + acc[1].y) + (acc[2].y + acc[3].y);
        s.z = (acc[0].z + acc[1].z) + (acc[2].z + acc[3].z);
        s.w = (acc[0].w + acc[1].w) + (acc[2].w + acc[3].w);
        int col = wn * 8 + 2 * t;
        int row0 = nb + wm * 16 + g;
        if (row0 < N_NODES)
            *(float2*)&g_xld[(size_t)row0 * 32 + col] = make_float2(s.x, s.y);
        if (row0 + 8 < N_NODES)
            *(float2*)&g_xld[(size_t)(row0 + 8) * 32 + col] = make_float2(s.z, s.w);
    } else {
        size_t i0 = (size_t)(b - 1875) * 256 + tid;
        size_t step = (size_t)1024 * 256;
        size_t n4 = (size_t)N_NODES * WIDTH / 4;
        float4* p = (float4*)g_aggx;
        for (size_t i = i0; i < n4; i += step)
            p[i] = make_float4(0.f, 0.f, 0.f, 0.f);
        size_t m4 = (size_t)N_NODES * DIM_HEAD / 4;
        float4* q4 = (float4*)g_t2;
        for (size_t i = i0; i < m4; i += step)
            q4[i] = make_float4(0.f, 0.f, 0.f, 0.f);
        for (size_t i = i0; i < N_NODES; i += step)
            g_indeg[i] = 0;
    }
}

// ---------------------------------------------------------------------------
// work_kernel: blocks [0,144) W2 gemm+swizzle ; [144,400) gate/value swizzle ;
// [400,528) post swizzle ; [528,8028) edge.  (prep first so it overlaps the
// many DRAM-bound edge waves instead of forming a tail)
// ---------------------------------------------------------------------------
__global__ __launch_bounds__(256) void work_kernel(
    const float* __restrict__ x,
    const int*   __restrict__ edge_idx,
    const int*   __restrict__ edge_attr,
    const float* __restrict__ node_elec,
    const float* __restrict__ emb_edge,
    const float* __restrict__ moa_w,
    const float* __restrict__ moa_s,
    const float* __restrict__ elec_lin,
    const float* __restrict__ lin_pre,
    const float* __restrict__ lora_up,
    const float* __restrict__ gate_lin,
    const float* __restrict__ value_lin,
    const float* __restrict__ gate_kernel,
    const float* __restrict__ value_kernel,
    const float* __restrict__ post_kernel)
{
    __shared__ int   s_i0[32], s_i1[32];
    __shared__ float emb_s[32][33];

    const int b = blockIdx.x, tid = threadIdx.x;

    if (b >= 528) {
        const int eb = (b - 528) * 32;
        if (tid < 32) {
            int i0 = edge_idx[eb + tid];
            int i1 = edge_idx[N_EDGES + eb + tid];
            s_i0[tid] = i0;
            s_i1[tid] = i1;
            atomicAdd(&g_indeg[i1], 1);
        }
        __syncthreads();
        {
            const int wid = tid >> 5, lane = tid & 31;
            float w0 = sp(moa_w[lane]);
            float w1 = sp(moa_w[32 + lane]);
            w0 /= wsum(w0);
            w1 /= wsum(w1);
            const float s0  = sp(moa_s[lane]);
            const float s1  = sp(moa_s[32 + lane]);
            const float el0 = elec_lin[lane];
            const float el1 = elec_lin[32 + lane];
#pragma unroll
            for (int i = 0; i < 4; i++) {
                int e  = wid * 4 + i;
                int i0 = s_i0[e], i1 = s_i1[e];
                float d0 = node_elec[2 * i0]     - node_elec[2 * i1];
                float d1 = node_elec[2 * i0 + 1] - node_elec[2 * i1 + 1];
                float m0 = wsum(tanhf(d0 * s0) * w0);
                float m1 = wsum(tanhf(d1 * s1) * w1);
                int ge = eb + e;
                int a0 = edge_attr[3 * ge], a1 = edge_attr[3 * ge + 1],
                    a2 = edge_attr[3 * ge + 2];
                emb_s[e][lane] = emb_edge[a0 * 32 + lane] + emb_edge[a1 * 32 + lane] +
                                 emb_edge[a2 * 32 + lane] + m0 * el0 + m1 * el1;
            }
        }
        __syncthreads();

        const int e  = tid >> 3;
        const int i0 = s_i0[e], i1 = s_i1[e];
        {
            const int d = (tid & 7) * 4;
            float4 a = __ldg((const float4*)(g_xld + (size_t)i0 * 32 + d));
            float4 bb = __ldg((const float4*)(g_xld + (size_t)i1 * 32 + d));
            float4 t;
            t.x = (a.x + bb.x) * emb_s[e][d + 0];
            t.y = (a.y + bb.y) * emb_s[e][d + 1];
            t.z = (a.z + bb.z) * emb_s[e][d + 2];
            t.w = (a.w + bb.w) * emb_s[e][d + 3];
            red_add_v4(g_t2 + (size_t)i1 * 32 + d, t);
        }
        {
            const int c0 = (tid & 7) * 4;
            const float4* xr = (const float4*)(x + (size_t)i0 * WIDTH);
            float* dst = g_aggx + (size_t)i1 * WIDTH;
#pragma unroll
            for (int it = 0; it < 8; it++) {
                int c = c0 + it * 32;
                float4 v = __ldg(&xr[c >> 2]);
                red_add_v4(dst + c, v);
            }
        }
    } else if (b < 144) {
        int id = b * 256 + tid;            // 36864
        int k  = id >> 7;                  // 0..287
        int n  = (id & 127) * 4;           // 0..508
        const float* srow = (k < 256) ? (lin_pre + k * 256)
                                      : (lora_up + (k - 256) * 256);
        const float* M = (n < 256) ? gate_lin : value_lin;
        int nn = n & 255;
        float4 acc = make_float4(0.f, 0.f, 0.f, 0.f);
#pragma unroll 4
        for (int j = 0; j < 256; j++) {
            float  s = __ldg(&srow[j]);
            float4 m = __ldg((const float4*)(M + j * 256 + nn));
            acc.x += s * m.x; acc.y += s * m.y;
            acc.z += s * m.z; acc.w += s * m.w;
        }
        int ks = k >> 3, kin = k & 7, tig = kin & 3, jj = kin >> 2;
        float v[4] = {acc.x, acc.y, acc.z, acc.w};
#pragma unroll
        for (int q = 0; q < 4; q++) {
            int nq = n + q;
            int idx = ((ks * 64 + (nq >> 3)) * 32 + ((nq & 7) * 4 + tig)) * 2 + jj;
            g_W2f[idx] = tf32r(v[q]);
        }
    } else if (b < 400) {
        int id = (b - 144) * 256 + tid;    // 65536
        int path = id >> 15;
        int h    = (id >> 12) & 7;
        int d    = (id >> 7) & 31;
        int f    = id & 127;
        float val = path ? __ldg(&value_kernel[h * 4096 + d * 128 + f])
                         : __ldg(&gate_kernel [h * 4096 + d * 128 + f]);
        int ks = d >> 3, kin = d & 7, tig = kin & 3, jj = kin >> 2;
        int nt = f >> 3, g = f & 7;
        int idx = (((((path * 8 + h) * 4 + ks) * 16 + nt) * 32) + (g * 4 + tig)) * 2 + jj;
        g_GVf[idx] = tf32r(val);
    } else {
        int p = (b - 400) * 256 + tid;     // 32768
        int h = p >> 12;
        int f = (p >> 5) & 127;
        int d2 = p & 31;
        float val = __ldg(&post_kernel[h * 4096 + f * 32 + d2]);
        int ks = f >> 3, kin = f & 7, tig = kin & 3, jj = kin >> 2;
        int nt = d2 >> 3, g = d2 & 7;
        int idx = ((((h * 16 + ks) * 4 + nt) * 32) + (g * 4 + tig)) * 2 + jj;
        g_Pf[idx] = tf32r(val);
    }
}

// ---------------------------------------------------------------------------
// Node kernel: persistent grid (296 blocks), grid-stride over 1875 tiles of
// 32 nodes; 256 threads, 2 blocks/SM.  Round-14 per-tile body.
// ---------------------------------------------------------------------------
__global__ __launch_bounds__(256) void node_kernel(
    const float* __restrict__ x,
    const int*   __restrict__ deg,
    const float* __restrict__ emb_deg,
    const float* __restrict__ act_bias,
    float*       __restrict__ out)
{
    extern __shared__ float sm[];
    float* A_s   = sm;                    // [32][292]
    float* u_s   = sm + 32 * 292;         // [32][260]
    float* v_s   = u_s + 32 * 260;        // [32][260]
    float* avv_s = A_s;                   // 2 x [32][132]

    const int tid  = threadIdx.x;
    const int lane = tid & 31, wid = tid >> 5;
    const int g = lane >> 2, t = lane & 3;
    const float CLIP_LO = 0.22360679774997896f;
    const float CLIP_HI = 4.47213595499957939f;

    for (int tile = blockIdx.x; tile < NTILES; tile += NODE_GRID) {
        const int nb = tile * MTILE;

        // --- stage inputs (tf32-rounded): raw agg | t2 ---
        {
            const int n  = tid >> 3;
            const int c0 = (tid & 7) * 4;
            const int gcl = min(nb + n, N_NODES - 1);
            const float idg = (float)__ldg(&g_indeg[gcl]);
            const float* ra = g_aggx + (size_t)gcl * WIDTH;
            const float* rx = x + (size_t)gcl * WIDTH;
#pragma unroll
            for (int it = 0; it < 8; it++) {
                int c = c0 + it * 32;
                float4 a  = *(const float4*)(ra + c);
                float4 xv = __ldg((const float4*)(rx + c));
                A_s[n * 292 + c + 0] = tf32r(a.x + idg * xv.x);
                A_s[n * 292 + c + 1] = tf32r(a.y + idg * xv.y);
                A_s[n * 292 + c + 2] = tf32r(a.z + idg * xv.z);
                A_s[n * 292 + c + 3] = tf32r(a.w + idg * xv.w);
            }
            float4 t2v = *(const float4*)(g_t2 + (size_t)gcl * 32 + c0);
            A_s[n * 292 + 256 + c0 + 0] = tf32r(t2v.x);
            A_s[n * 292 + 256 + c0 + 1] = tf32r(t2v.y);
            A_s[n * 292 + 256 + c0 + 2] = tf32r(t2v.z);
            A_s[n * 292 + 256 + c0 + 3] = tf32r(t2v.w);
        }
        __syncthreads();

        // --- Stage A: [32x288] @ W2[288x512] -> U|V with fused RMS norm ---
        {
            const int wn = wid;                // 0..7, 64 cols each
            const unsigned* Au = (const unsigned*)A_s;
            float4 acc[2][8];
#pragma unroll
            for (int mf = 0; mf < 2; mf++)
#pragma unroll
                for (int nt = 0; nt < 8; nt++)
                    acc[mf][nt] = make_float4(0.f, 0.f, 0.f, 0.f);

            const uint2* Bp = ((const uint2*)g_W2f) + (wn * 8) * 32 + lane;
#pragma unroll 6
            for (int ks = 0; ks < 36; ks++) {
                int kc = ks * 8 + t;
                unsigned a0[2], a1[2], a2[2], a3[2];
#pragma unroll
                for (int mf = 0; mf < 2; mf++) {
                    int r = (mf * 16 + g) * 292;
                    a0[mf] = Au[r + kc];
                    a1[mf] = Au[r + 2336 + kc];        // +8 rows
                    a2[mf] = Au[r + kc + 4];
                    a3[mf] = Au[r + 2336 + kc + 4];
                }
                const uint2* Bks = Bp + ks * 64 * 32;
#pragma unroll
                for (int nt = 0; nt < 8; nt++) {
                    uint2 bb = __ldg(Bks + nt * 32);
#pragma unroll
                    for (int mf = 0; mf < 2; mf++)
                        mma_tf32(acc[mf][nt], a0[mf], a1[mf], a2[mf], a3[mf],
                                 bb.x, bb.y);
                }
            }

            // fused RMS epilogue: cols of one head live in lanes g*4+{0..3}
            const bool isU = (wn < 4);
            float* dst = isU ? u_s : v_s;
            const int cb = (wn & 3) * 64;
            const float inv_s2 = 0.70710678118654752440f;
#pragma unroll
            for (int mf = 0; mf < 2; mf++) {
                const int rA = mf * 16 + g;
                const int rB = rA + 8;
                int dgA = 0, dgB = 0;
                if (isU) {
                    dgA = __ldg(&deg[min(nb + rA, N_NODES - 1)]) * 256;
                    dgB = __ldg(&deg[min(nb + rB, N_NODES - 1)]) * 256;
                }
#pragma unroll
                for (int hh = 0; hh < 2; hh++) {
                    float sA = 0.f, sB = 0.f;
#pragma unroll
                    for (int j = 0; j < 4; j++) {
                        float4 a = acc[mf][hh * 4 + j];
                        sA += a.x * a.x + a.y * a.y;
                        sB += a.z * a.z + a.w * a.w;
                    }
                    sA += __shfl_xor_sync(0xffffffffu, sA, 1);
                    sA += __shfl_xor_sync(0xffffffffu, sA, 2);
                    sB += __shfl_xor_sync(0xffffffffu, sB, 1);
                    sB += __shfl_xor_sync(0xffffffffu, sB, 2);
                    float rinvA = rsqrtf(sA * (1.f / 32.f) + 1e-6f);
                    float rinvB = rsqrtf(sB * (1.f / 32.f) + 1e-6f);
#pragma unroll
                    for (int j = 0; j < 4; j++) {
                        float4 a = acc[mf][hh * 4 + j];
                        int c = cb + (hh * 4 + j) * 8 + 2 * t;
                        if (isU) {
                            float2 bA = __ldg((const float2*)(emb_deg + dgA + c));
                            float2 bB = __ldg((const float2*)(emb_deg + dgB + c));
                            *(float2*)&dst[rA * 260 + c] = make_float2(
                                tf32r((a.x * rinvA + bA.x) * inv_s2),
                                tf32r((a.y * rinvA + bA.y) * inv_s2));
                            *(float2*)&dst[rB * 260 + c] = make_float2(
                                tf32r((a.z * rinvB + bB.x) * inv_s2),
                                tf32r((a.w * rinvB + bB.y) * inv_s2));
                        } else {
                            *(float2*)&dst[rA * 260 + c] = make_float2(
                                tf32r(a.x * rinvA), tf32r(a.y * rinvA));
                            *(float2*)&dst[rB * 260 + c] = make_float2(
                                tf32r(a.z * rinvB), tf32r(a.w * rinvB));
                        }
                    }
                }
            }
        }
        __syncthreads();

        const unsigned* U32 = (const unsigned*)u_s;
        const unsigned* V32 = (const unsigned*)v_s;

#pragma unroll 1
        for (int hp = 0; hp < 4; hp++) {
            // --- Stage B: 8 warps = 2 heads x 4 Nquarter ---
            {
                const int sub = wid >> 2;
                const int nq  = wid & 3;
                const int h   = hp * 2 + sub;
                float* avv = avv_s + sub * (32 * 132);

                float4 ag[2][4], av4[2][4];
#pragma unroll
                for (int mf = 0; mf < 2; mf++)
#pragma unroll
                    for (int j = 0; j < 4; j++) {
                        ag[mf][j]  = make_float4(0.f, 0.f, 0.f, 0.f);
                        av4[mf][j] = make_float4(0.f, 0.f, 0.f, 0.f);
                    }
#pragma unroll
                for (int ks = 0; ks < 4; ks++) {
                    int col = h * 32 + ks * 8 + t;
                    unsigned ua0[2], ua1[2], ua2[2], ua3[2];
                    unsigned va0[2], va1[2], va2[2], va3[2];
#pragma unroll
                    for (int mf = 0; mf < 2; mf++) {
                        int r = (mf * 16 + g) * 260;
                        ua0[mf] = U32[r + col];        ua1[mf] = U32[r + 2080 + col];
                        ua2[mf] = U32[r + col + 4];    ua3[mf] = U32[r + 2080 + col + 4];
                        va0[mf] = V32[r + col];        va1[mf] = V32[r + 2080 + col];
                        va2[mf] = V32[r + col + 4];    va3[mf] = V32[r + 2080 + col + 4];
                    }
#pragma unroll
                    for (int j = 0; j < 4; j++) {
                        int nt16 = nq * 4 + j;
                        uint2 bg = __ldg(((const uint2*)g_GVf) +
                                         ((h * 4 + ks) * 16 + nt16) * 32 + lane);
                        uint2 bv = __ldg(((const uint2*)g_GVf) +
                                         (((8 + h) * 4 + ks) * 16 + nt16) * 32 + lane);
#pragma unroll
                        for (int mf = 0; mf < 2; mf++) {
                            mma_tf32(ag[mf][j],  ua0[mf], ua1[mf], ua2[mf], ua3[mf], bg.x, bg.y);
                            mma_tf32(av4[mf][j], va0[mf], va1[mf], va2[mf], va3[mf], bv.x, bv.y);
                        }
                    }
                }
#pragma unroll
                for (int j = 0; j < 4; j++) {
                    int c = nq * 32 + j * 8 + 2 * t;
                    float2 bias = __ldg((const float2*)(act_bias + h * 128 + c));
#pragma unroll
                    for (int mf = 0; mf < 2; mf++) {
                        int r = (mf * 16 + g) * 132;
                        float o0 = fminf(fmaxf(sp(ag[mf][j].x + bias.x), CLIP_LO), CLIP_HI) * av4[mf][j].x;
                        float o1 = fminf(fmaxf(sp(ag[mf][j].y + bias.y), CLIP_LO), CLIP_HI) * av4[mf][j].y;
                        float o2 = fminf(fmaxf(sp(ag[mf][j].z + bias.x), CLIP_LO), CLIP_HI) * av4[mf][j].z;
                        float o3 = fminf(fmaxf(sp(ag[mf][j].w + bias.y), CLIP_LO), CLIP_HI) * av4[mf][j].w;
                        avv[r + c + 0]        = tf32r(o0);
                        avv[r + c + 1]        = tf32r(o1);
                        avv[r + 1056 + c + 0] = tf32r(o2);
                        avv[r + 1056 + c + 1] = tf32r(o3);
                    }
                }
            }
            __syncthreads();

            // --- Stage D: 8 warps = 2 heads x 4 col8 (2 rotating accs) ---
            {
                const int sub = wid >> 2;
                const int c8  = wid & 3;
                const int h   = hp * 2 + sub;
                const unsigned* AV = (const unsigned*)(avv_s + sub * (32 * 132));
                float4 dacc[2][2];
#pragma unroll
                for (int mf = 0; mf < 2; mf++) {
                    dacc[mf][0] = make_float4(0.f, 0.f, 0.f, 0.f);
                    dacc[mf][1] = make_float4(0.f, 0.f, 0.f, 0.f);
                }
#pragma unroll
                for (int ks = 0; ks < 16; ks++) {
                    int kc = ks * 8 + t;
                    uint2 bb = __ldg(((const uint2*)g_Pf) +
                                     ((h * 16 + ks) * 4 + c8) * 32 + lane);
#pragma unroll
                    for (int mf = 0; mf < 2; mf++) {
                        int r = (mf * 16 + g) * 132;
                        mma_tf32(dacc[mf][ks & 1], AV[r + kc], AV[r + 1056 + kc],
                                 AV[r + kc + 4], AV[r + 1056 + kc + 4], bb.x, bb.y);
                    }
                }
                int col = h * 32 + c8 * 8 + 2 * t;
#pragma unroll
                for (int mf = 0; mf < 2; mf++) {
                    float4 d0 = dacc[mf][0], d1 = dacc[mf][1];
                    float4 s = make_float4(d0.x + d1.x, d0.y + d1.y,
                                           d0.z + d1.z, d0.w + d1.w);
                    int row0 = nb + mf * 16 + g;
                    if (row0 < N_NODES)
                        *(float2*)&out[(size_t)row0 * WIDTH + col] =
                            make_float2(s.x, s.y);
                    if (row0 + 8 < N_NODES)
                        *(float2*)&out[(size_t)(row0 + 8) * WIDTH + col] =
                            make_float2(s.z, s.w);
                }
            }
            __syncthreads();
        }
    }
}

// ---------------------------------------------------------------------------
// Launch
// ---------------------------------------------------------------------------
extern "C" void kernel_launch(void* const* d_in, const int* in_sizes, int n_in,
                              void* d_out, int out_size) {
    const float* x            = (const float*)d_in[0];
    const int*   deg          = (const int*)  d_in[1];
    const int*   edge_idx     = (const int*)  d_in[2];
    const int*   edge_attr    = (const int*)  d_in[3];
    const float* node_elec    = (const float*)d_in[4];
    const float* lora_down    = (const float*)d_in[5];
    const float* lora_up      = (const float*)d_in[6];
    const float* emb_edge     = (const float*)d_in[7];
    const float* moa_w        = (const float*)d_in[8];
    const float* moa_s        = (const float*)d_in[9];
    const float* elec_lin     = (const float*)d_in[10];
    const float* emb_deg      = (const float*)d_in[11];
    const float* lin_pre      = (const float*)d_in[12];
    const float* gate_lin     = (const float*)d_in[13];
    const float* gate_kernel  = (const float*)d_in[14];
    const float* value_lin    = (const float*)d_in[15];
    const float* value_kernel = (const float*)d_in[16];
    const float* act_bias     = (const float*)d_in[17];
    const float* post_kernel  = (const float*)d_in[18];
    float* out = (float*)d_out;

    size_t ism = (size_t)32 * 260 * sizeof(float);   // 33280 B
    init_kernel<<<1875 + 1024, 256, ism>>>(x, lora_down);

    work_kernel<<<8028, 256>>>(
        x, edge_idx, edge_attr, node_elec,
        emb_edge, moa_w, moa_s, elec_lin,
        lin_pre, lora_up, gate_lin, value_lin,
        gate_kernel, value_kernel, post_kernel);

    size_t nsm = ((size_t)32 * 292 + 2 * 32 * 260) * sizeof(float);  // 103936 B
    cudaFuncSetAttribute(node_kernel,
                         cudaFuncAttributeMaxDynamicSharedMemorySize, (int)nsm);
    node_kernel<<<NODE_GRID, 256, nsm>>>(
        x, deg, emb_deg, act_bias, out);
}